// round 4
// baseline (speedup 1.0000x reference)
#include <cuda_runtime.h>
#include <cuda_bf16.h>
#include <math.h>

#define BATCH    16384
#define N_DENSE  13
#define N_TAB    26
#define ROWS_PB  64         // rows per block
#define THREADS  64
#define VOCAB    1000000

// Coalesced staging of indices + dense features through smem kills the
// divergent-stride index/dense LDG wavefronts (they were ~55% of L1tex
// traffic). Only the inherently random embedding gathers stay divergent.
__global__ __launch_bounds__(THREADS)
void dlrm_fused_kernel(
    const float*      __restrict__ xd,    // [B,13]
    const void*       __restrict__ xc_v,  // [B,26] int32 or int64
    const float*      __restrict__ emb,   // [26, V, 2]
    const float*      __restrict__ bw1,   // [13,3]
    const float*      __restrict__ bb1,   // [3]
    const float*      __restrict__ bw2,   // [3,2]
    const float*      __restrict__ bb2,   // [2]
    const float*      __restrict__ tw1,   // [54,4]
    const float*      __restrict__ tb1,   // [4]
    const float*      __restrict__ tw2,   // [4,2]
    const float*      __restrict__ tb2,   // [2]
    const float*      __restrict__ tw3,   // [2,1]
    const float*      __restrict__ tb3,   // [1]
    float*            __restrict__ out)   // [B,1]
{
    // indices stored narrowed to int32, row stride padded to 27 (gcd(27,32)=1
    // -> conflict-free LDS); dense padded to 14 (degree-2, negligible)
    __shared__ int   s_idx[ROWS_PB * 27];
    __shared__ float s_xd [ROWS_PB * 14];
    __shared__ float s_bw1[39], s_bb1[3], s_bw2[6], s_bb2[2];
    __shared__ float s_tw1[216], s_tb1[4], s_tw2[8], s_tb2[2], s_tw3[2], s_tb3[1];

    const int t = threadIdx.x;             // 0..63

    // ---- index-width probe (warp ballot on high words of first 32 slots;
    // values < 1e6 so real int64 has zero high words; int32 reinterpreted has
    // random high words, P(miss) ~ 1e-192) ----
    const unsigned long long pv = ((const unsigned long long*)xc_v)[t & 31];
    const unsigned hi = __ballot_sync(0xffffffffu, (pv >> 32) != 0ull);
    const bool is64 = (hi == 0u);

    // ---- stage weights ----
    for (int i = t; i < 39;  i += THREADS) s_bw1[i] = bw1[i];
    for (int i = t; i < 216; i += THREADS) s_tw1[i] = tw1[i];
    if (t < 3)  s_bb1[t] = bb1[t];
    if (t < 6)  s_bw2[t] = bw2[t];
    if (t < 2)  s_bb2[t] = bb2[t];
    if (t < 4)  s_tb1[t] = tb1[t];
    if (t < 8)  s_tw2[t] = tw2[t];
    if (t < 2)  s_tb2[t] = tb2[t];
    if (t < 2)  s_tw3[t] = tw3[t];
    if (t == 0) s_tb3[0] = tb3[0];

    const int row0 = blockIdx.x * ROWS_PB;

    // ---- stage x_cat: contiguous slab, int4 coalesced loads ----
    if (is64) {
        // 64 rows * 26 int64 = 1664 elems = 832 int4 chunks (2 elems each)
        const int4* g = (const int4*)((const long long*)xc_v + (long long)row0 * N_TAB);
        #pragma unroll
        for (int j = t; j < (ROWS_PB * N_TAB) / 2; j += THREADS) {
            int4 v = g[j];                 // elems 2j (v.x=lo), 2j+1 (v.z=lo)
            int e0 = 2 * j, e1 = 2 * j + 1;
            s_idx[(e0 / N_TAB) * 27 + (e0 % N_TAB)] = v.x;
            s_idx[(e1 / N_TAB) * 27 + (e1 % N_TAB)] = v.z;
        }
    } else {
        // 1664 int32 = 416 int4 chunks (4 elems each)
        const int4* g = (const int4*)((const int*)xc_v + (long long)row0 * N_TAB);
        for (int j = t; j < (ROWS_PB * N_TAB) / 4; j += THREADS) {
            int4 v = g[j];
            int e0 = 4 * j;
            s_idx[((e0 + 0) / N_TAB) * 27 + ((e0 + 0) % N_TAB)] = v.x;
            s_idx[((e0 + 1) / N_TAB) * 27 + ((e0 + 1) % N_TAB)] = v.y;
            s_idx[((e0 + 2) / N_TAB) * 27 + ((e0 + 2) % N_TAB)] = v.z;
            s_idx[((e0 + 3) / N_TAB) * 27 + ((e0 + 3) % N_TAB)] = v.w;
        }
    }

    // ---- stage x_dense: 64 rows * 13 f32 = 832 = 208 float4 chunks ----
    {
        const float4* g = (const float4*)(xd + (long long)row0 * N_DENSE);
        for (int j = t; j < (ROWS_PB * N_DENSE) / 4; j += THREADS) {
            float4 v = g[j];
            int e0 = 4 * j;
            s_xd[((e0 + 0) / N_DENSE) * 14 + ((e0 + 0) % N_DENSE)] = v.x;
            s_xd[((e0 + 1) / N_DENSE) * 14 + ((e0 + 1) % N_DENSE)] = v.y;
            s_xd[((e0 + 2) / N_DENSE) * 14 + ((e0 + 2) % N_DENSE)] = v.z;
            s_xd[((e0 + 3) / N_DENSE) * 14 + ((e0 + 3) % N_DENSE)] = v.w;
        }
    }

    __syncthreads();

    // ---- issue all 26 independent random gathers (the only divergent LDGs) ----
    const int* ip = s_idx + t * 27;
    float2 e[N_TAB];
    #pragma unroll
    for (int k = 0; k < N_TAB; k++) {
        int idx = ip[k];
        e[k] = __ldcg(reinterpret_cast<const float2*>(
            emb + ((long long)k * VOCAB + idx) * 2));
    }

    // ---- bottom MLP: 13 -> 3 -> 2, relu ----
    const float* xr = s_xd + t * 14;
    float d1[3];
    #pragma unroll
    for (int h = 0; h < 3; h++) {
        float acc = s_bb1[h];
        #pragma unroll
        for (int i = 0; i < N_DENSE; i++) acc = fmaf(xr[i], s_bw1[i * 3 + h], acc);
        d1[h] = fmaxf(acc, 0.0f);
    }
    float d2[2];
    #pragma unroll
    for (int o = 0; o < 2; o++) {
        float acc = s_bb2[o];
        #pragma unroll
        for (int h = 0; h < 3; h++) acc = fmaf(d1[h], s_bw2[h * 2 + o], acc);
        d2[o] = fmaxf(acc, 0.0f);
    }

    // ---- top MLP: concat([d2, e]) -> 4 -> 2 -> 1, sigmoid ----
    float h1[4];
    #pragma unroll
    for (int o = 0; o < 4; o++) {
        float acc = fmaf(d2[1], s_tw1[1 * 4 + o],
                    fmaf(d2[0], s_tw1[0 * 4 + o], s_tb1[o]));
        #pragma unroll
        for (int k = 0; k < N_TAB; k++) {
            acc = fmaf(e[k].x, s_tw1[(2 + 2 * k) * 4 + o], acc);
            acc = fmaf(e[k].y, s_tw1[(3 + 2 * k) * 4 + o], acc);
        }
        h1[o] = fmaxf(acc, 0.0f);
    }
    float h2[2];
    #pragma unroll
    for (int o = 0; o < 2; o++) {
        float acc = s_tb2[o];
        #pragma unroll
        for (int j = 0; j < 4; j++) acc = fmaf(h1[j], s_tw2[j * 2 + o], acc);
        h2[o] = fmaxf(acc, 0.0f);
    }
    float z = s_tb3[0];
    z = fmaf(h2[0], s_tw3[0], z);
    z = fmaf(h2[1], s_tw3[1], z);

    out[row0 + t] = 1.0f / (1.0f + __expf(-z));
}

extern "C" void kernel_launch(void* const* d_in, const int* in_sizes, int n_in,
                              void* d_out, int out_size) {
    const float*     xd  = (const float*)d_in[0];
    const void*      xc  = d_in[1];
    const float*     emb = (const float*)d_in[2];
    const float*     bw1 = (const float*)d_in[3];
    const float*     bb1 = (const float*)d_in[4];
    const float*     bw2 = (const float*)d_in[5];
    const float*     bb2 = (const float*)d_in[6];
    const float*     tw1 = (const float*)d_in[7];
    const float*     tb1 = (const float*)d_in[8];
    const float*     tw2 = (const float*)d_in[9];
    const float*     tb2 = (const float*)d_in[10];
    const float*     tw3 = (const float*)d_in[11];
    const float*     tb3 = (const float*)d_in[12];
    float*           out = (float*)d_out;

    dlrm_fused_kernel<<<BATCH / ROWS_PB, THREADS>>>(
        xd, xc, emb, bw1, bb1, bw2, bb2,
        tw1, tb1, tw2, tb2, tw3, tb3, out);
}

// round 5
// speedup vs baseline: 1.1910x; 1.1910x over previous
#include <cuda_runtime.h>
#include <cuda_bf16.h>
#include <math.h>

#define BATCH    16384
#define N_DENSE  13
#define N_TAB    26
#define VOCAB    1000000
#define THREADS  64            // 2 independent warps per block
#define ROWS_PW  32            // rows per warp
#define ROWS_PB  (ROWS_PW * (THREADS / 32))

// Per-WARP coalesced staging of indices + dense through private smem slabs
// (no block-wide sync -> no serialization bubble). Only the inherently
// random embedding gathers remain divergent.
__global__ __launch_bounds__(THREADS)
void dlrm_fused_kernel(
    const float*      __restrict__ xd,    // [B,13]
    const void*       __restrict__ xc_v,  // [B,26] int32 or int64
    const float*      __restrict__ emb,   // [26, V, 2]
    const float*      __restrict__ bw1,   // [13,3]
    const float*      __restrict__ bb1,   // [3]
    const float*      __restrict__ bw2,   // [3,2]
    const float*      __restrict__ bb2,   // [2]
    const float*      __restrict__ tw1,   // [54,4]
    const float*      __restrict__ tb1,   // [4]
    const float*      __restrict__ tw2,   // [4,2]
    const float*      __restrict__ tb2,   // [2]
    const float*      __restrict__ tw3,   // [2,1]
    const float*      __restrict__ tb3,   // [1]
    float*            __restrict__ out)   // [B,1]
{
    // per-warp slabs; idx row stride 27 (gcd(27,32)=1 -> conflict-free LDS)
    __shared__ int   s_idx[THREADS / 32][ROWS_PW * 27];
    __shared__ float s_xd [THREADS / 32][ROWS_PW * 14];
    __shared__ float s_w[283];   // bw1(39),bb1(3),bw2(6),bb2(2),tw1(216),tb1(4),tw2(8),tb2(2),tw3(2),tb3(1)

    const int t    = threadIdx.x;
    const int w    = t >> 5;           // warp id in block
    const int lane = t & 31;

    // ---- index-width probe: first 32 int64 slots; values < 1e6 so genuine
    // int64 has zero high words; int32 reinterpreted has random high words ----
    const unsigned long long pv = ((const unsigned long long*)xc_v)[lane];
    const unsigned hi = __ballot_sync(0xffffffffu, (pv >> 32) != 0ull);
    const bool is64 = (hi == 0u);

    // ---- stage all weights as one packed coalesced strip ----
    {
        const float* srcs[10] = {bw1, bb1, bw2, bb2, tw1, tb1, tw2, tb2, tw3, tb3};
        const int    lens[10] = {39, 3, 6, 2, 216, 4, 8, 2, 2, 1};
        int off = 0;
        #pragma unroll
        for (int s = 0; s < 10; s++) {
            for (int i = t; i < lens[s]; i += THREADS) s_w[off + i] = srcs[s][i];
            off += lens[s];
        }
    }
    const float* s_bw1 = s_w;          // 39
    const float* s_bb1 = s_w + 39;     // 3
    const float* s_bw2 = s_w + 42;     // 6
    const float* s_bb2 = s_w + 48;     // 2
    const float* s_tw1 = s_w + 50;     // 216
    const float* s_tb1 = s_w + 266;    // 4
    const float* s_tw2 = s_w + 270;    // 8
    const float* s_tb2 = s_w + 278;    // 2
    const float* s_tw3 = s_w + 280;    // 2
    const float* s_tb3 = s_w + 282;    // 1

    const int wrow0 = blockIdx.x * ROWS_PB + w * ROWS_PW;  // warp's first row

    // ---- per-warp coalesced staging of x_cat (narrowed to int32) ----
    if (is64) {
        // 32 rows * 26 int64 = 832 ull = 416 longlong2 (13 per lane)
        const longlong2* g =
            (const longlong2*)((const long long*)xc_v + (long long)wrow0 * N_TAB);
        #pragma unroll
        for (int j = lane; j < (ROWS_PW * N_TAB) / 2; j += 32) {
            longlong2 v = g[j];
            int e0 = 2 * j, e1 = 2 * j + 1;
            s_idx[w][(e0 / N_TAB) * 27 + (e0 % N_TAB)] = (int)v.x;
            s_idx[w][(e1 / N_TAB) * 27 + (e1 % N_TAB)] = (int)v.y;
        }
    } else {
        // 832 int32 = 208 int4 (6.5 per lane)
        const int4* g = (const int4*)((const int*)xc_v + (long long)wrow0 * N_TAB);
        for (int j = lane; j < (ROWS_PW * N_TAB) / 4; j += 32) {
            int4 v = g[j];
            int e0 = 4 * j;
            s_idx[w][((e0 + 0) / N_TAB) * 27 + ((e0 + 0) % N_TAB)] = v.x;
            s_idx[w][((e0 + 1) / N_TAB) * 27 + ((e0 + 1) % N_TAB)] = v.y;
            s_idx[w][((e0 + 2) / N_TAB) * 27 + ((e0 + 2) % N_TAB)] = v.z;
            s_idx[w][((e0 + 3) / N_TAB) * 27 + ((e0 + 3) % N_TAB)] = v.w;
        }
    }

    // ---- per-warp coalesced staging of x_dense: 416 floats = 104 float4 ----
    {
        const float4* g = (const float4*)(xd + (long long)wrow0 * N_DENSE);
        #pragma unroll
        for (int j = lane; j < (ROWS_PW * N_DENSE) / 4; j += 32) {
            float4 v = g[j];
            int e0 = 4 * j;
            s_xd[w][((e0 + 0) / N_DENSE) * 14 + ((e0 + 0) % N_DENSE)] = v.x;
            s_xd[w][((e0 + 1) / N_DENSE) * 14 + ((e0 + 1) % N_DENSE)] = v.y;
            s_xd[w][((e0 + 2) / N_DENSE) * 14 + ((e0 + 2) % N_DENSE)] = v.z;
            s_xd[w][((e0 + 3) / N_DENSE) * 14 + ((e0 + 3) % N_DENSE)] = v.w;
        }
    }

    __syncwarp();   // warp-local: staging visible to this warp's lanes

    // ---- issue all 26 independent random gathers ----
    const int* ip = s_idx[w] + lane * 27;
    float2 e[N_TAB];
    #pragma unroll
    for (int k = 0; k < N_TAB; k++) {
        int idx = ip[k];
        e[k] = __ldcg(reinterpret_cast<const float2*>(
            emb + ((long long)k * VOCAB + idx) * 2));
    }

    // NOTE: weights were written by all warps of the block into shared s_w.
    // Both warps write identical values (same source), so reading without a
    // block sync is safe only if this warp itself covered all 283 entries —
    // it did: the staging loop above strides by THREADS over t, covering all
    // entries cooperatively. To stay strictly correct without __syncthreads,
    // ensure each warp alone covers s_w: redo with lane-stride per warp.
    // (Handled below: s_w was filled with t-stride; add a cheap block sync
    // AFTER gathers are already in flight — LDGs above are issued, so the
    // sync does not delay them.)
    __syncthreads();

    // ---- bottom MLP: 13 -> 3 -> 2, relu ----
    const float* xr = s_xd[w] + lane * 14;
    float d1[3];
    #pragma unroll
    for (int h = 0; h < 3; h++) {
        float acc = s_bb1[h];
        #pragma unroll
        for (int i = 0; i < N_DENSE; i++) acc = fmaf(xr[i], s_bw1[i * 3 + h], acc);
        d1[h] = fmaxf(acc, 0.0f);
    }
    float d2[2];
    #pragma unroll
    for (int o = 0; o < 2; o++) {
        float acc = s_bb2[o];
        #pragma unroll
        for (int h = 0; h < 3; h++) acc = fmaf(d1[h], s_bw2[h * 2 + o], acc);
        d2[o] = fmaxf(acc, 0.0f);
    }

    // ---- top MLP: concat([d2, e]) -> 4 -> 2 -> 1, sigmoid ----
    float h1[4];
    #pragma unroll
    for (int o = 0; o < 4; o++) {
        float acc = fmaf(d2[1], s_tw1[1 * 4 + o],
                    fmaf(d2[0], s_tw1[0 * 4 + o], s_tb1[o]));
        #pragma unroll
        for (int k = 0; k < N_TAB; k++) {
            acc = fmaf(e[k].x, s_tw1[(2 + 2 * k) * 4 + o], acc);
            acc = fmaf(e[k].y, s_tw1[(3 + 2 * k) * 4 + o], acc);
        }
        h1[o] = fmaxf(acc, 0.0f);
    }
    float h2[2];
    #pragma unroll
    for (int o = 0; o < 2; o++) {
        float acc = s_tb2[o];
        #pragma unroll
        for (int j = 0; j < 4; j++) acc = fmaf(h1[j], s_tw2[j * 2 + o], acc);
        h2[o] = fmaxf(acc, 0.0f);
    }
    float z = s_tb3[0];
    z = fmaf(h2[0], s_tw3[0], z);
    z = fmaf(h2[1], s_tw3[1], z);

    out[wrow0 + lane] = 1.0f / (1.0f + __expf(-z));
}

extern "C" void kernel_launch(void* const* d_in, const int* in_sizes, int n_in,
                              void* d_out, int out_size) {
    const float*     xd  = (const float*)d_in[0];
    const void*      xc  = d_in[1];
    const float*     emb = (const float*)d_in[2];
    const float*     bw1 = (const float*)d_in[3];
    const float*     bb1 = (const float*)d_in[4];
    const float*     bw2 = (const float*)d_in[5];
    const float*     bb2 = (const float*)d_in[6];
    const float*     tw1 = (const float*)d_in[7];
    const float*     tb1 = (const float*)d_in[8];
    const float*     tw2 = (const float*)d_in[9];
    const float*     tb2 = (const float*)d_in[10];
    const float*     tw3 = (const float*)d_in[11];
    const float*     tb3 = (const float*)d_in[12];
    float*           out = (float*)d_out;

    dlrm_fused_kernel<<<BATCH / ROWS_PB, THREADS>>>(
        xd, xc, emb, bw1, bb1, bw2, bb2,
        tw1, tb1, tw2, tb2, tw3, tb3, out);
}